// round 6
// baseline (speedup 1.0000x reference)
#include <cuda_runtime.h>
#include <cstdint>

#define OUTD 11008
#define IND  4096
#define GCNT 704512
#define CDIM 172
#define NB   8
#define ICHUNK 512
#define NIT  (ICHUNK / 32)

typedef unsigned long long ull;

// ---------------------------------------------------------------------------
__global__ void init_out_kernel(const float* __restrict__ bias,
                                float* __restrict__ out) {
    int idx = blockIdx.x * blockDim.x + threadIdx.x;
    if (idx < NB * OUTD) out[idx] = bias[idx % OUTD];
}

// packed f32x2 helpers (sm_100+)
__device__ __forceinline__ void fma2(ull& acc, ull a, ull b) {
    asm("fma.rn.f32x2 %0, %1, %2, %0;" : "+l"(acc) : "l"(a), "l"(b));
}
__device__ __forceinline__ ull add2(ull a, ull b) {
    ull r; asm("add.rn.f32x2 %0, %1, %2;" : "=l"(r) : "l"(a), "l"(b)); return r;
}
__device__ __forceinline__ ull pack2(float v) {
    ull r; asm("mov.b64 %0, {%1, %1};" : "=l"(r) : "f"(v)); return r;
}
__device__ __forceinline__ ull pack2f(float a, float b) {
    ull r; asm("mov.b64 %0, {%1, %2};" : "=l"(r) : "f"(a), "f"(b)); return r;
}

// ---------------------------------------------------------------------------
// Block = (c, i-chunk of 512, rowhalf). Warp w owns Wq rows rhbase+2w, +2w+1
// (=> 4 output rows via hi/lo nibbles). Lane = i offset -> coalesced loads.
// ---------------------------------------------------------------------------
__global__ __launch_bounds__(256, 3) void hqq_gemv_kernel(
    const int*   __restrict__ Wq,     // [32, 704512] int32 (one byte per elem)
    const float* __restrict__ scale,  // [704512]
    const float* __restrict__ zero,   // [704512]
    const float* __restrict__ x,      // [8, 4096]
    float*       __restrict__ out)    // [8, 11008]
{
    __shared__ ull xsm[4 * ICHUNK];                    // xp[pp][j], 16 KB

    const int tid = threadIdx.x;
    const int z   = blockIdx.x & 1;                    // rowhalf
    const int h   = (blockIdx.x >> 1) & 7;             // i-chunk
    const int c   = blockIdx.x >> 4;                   // 0..171
    const int ib  = h * ICHUNK;

    // Stage x as 4 batch-pair planes: xsm[pp*512 + j] = {x[2pp][ib+j], x[2pp+1][ib+j]}
    for (int k = tid; k < 4 * ICHUNK; k += 256) {
        int pp = k >> 9, j = k & (ICHUNK - 1);
        float lo = x[(2 * pp)     * IND + ib + j];
        float hi = x[(2 * pp + 1) * IND + ib + j];
        xsm[k] = pack2f(lo, hi);
    }
    __syncthreads();

    const int w  = tid >> 5;                           // warp 0..7
    const int l  = tid & 31;
    const int r0 = (z << 4) + (w << 1);                // first Wq row of warp
    const int g0 = c * IND + ib + l;

    const int*   qp = Wq + (long)r0 * GCNT + g0;       // row r0; row r0+1 = +GCNT
    const float* sp = scale + g0;
    const float* zp = zero  + g0;

    ull acc[16];
    #pragma unroll
    for (int i = 0; i < 16; ++i) acc[i] = 0ull;

    // prefetch iter 0
    float s_c = __ldg(sp), z_c = __ldg(zp);
    int qa = __ldg(qp), qb = __ldg(qp + GCNT);

    #pragma unroll 2
    for (int it = 0; it < NIT; ++it) {
        // prefetch next stripe (last iter: in-bounds re-read of stripe 0)
        const int nit = (it + 1 < NIT) ? (it + 1) : 0;
        const int off = nit * 32;
        float s_n = __ldg(sp + off), z_n = __ldg(zp + off);
        int qan = __ldg(qp + off), qbn = __ldg(qp + off + GCNT);

        // per-group constants (shared by both rows; groups are row-independent)
        const float t   = -z_c * s_c;                  // -z*s (small magnitude)
        const float s16 = s_c * 0.0625f;               // exact pow2 scaling

        // x batch pairs for this lane's group (4x LDS.64, conflict-free)
        const ull* xr = xsm + it * 32 + l;
        const ull x01 = xr[0], x23 = xr[ICHUNK], x45 = xr[2 * ICHUNK], x67 = xr[3 * ICHUNK];

        // Exact nibble extraction: f = int_as_float(nib|0x4B000000) - 8388608
        // gives nl (resp. 16*nh) EXACTLY; then one fma with small operands.
#define DOROW(QV, RP)                                                          \
        {                                                                      \
            float fl = __int_as_float(((QV) & 0x0F) | 0x4B000000) - 8388608.f; \
            float fh = __int_as_float(((QV) & 0xF0) | 0x4B000000) - 8388608.f; \
            float wl = fmaf(fl, s_c, t);                                       \
            float wh = fmaf(fh, s16, t);                                       \
            ull wh2 = pack2(wh), wl2 = pack2(wl);                              \
            fma2(acc[(RP)*8 + 0], x01, wh2); fma2(acc[(RP)*8 + 1], x23, wh2);  \
            fma2(acc[(RP)*8 + 2], x45, wh2); fma2(acc[(RP)*8 + 3], x67, wh2);  \
            fma2(acc[(RP)*8 + 4], x01, wl2); fma2(acc[(RP)*8 + 5], x23, wl2);  \
            fma2(acc[(RP)*8 + 6], x45, wl2); fma2(acc[(RP)*8 + 7], x67, wl2);  \
        }
        DOROW(qa, 0) DOROW(qb, 1)
#undef DOROW

        s_c = s_n; z_c = z_n; qa = qan; qb = qbn;
    }

    // Butterfly halving exchange: 16 f32x2 per lane -> lane l holds item l>>1,
    // summed over 16 lanes; final xor(1) completes the 32-lane sum.
    // item k: rp = k>>3, half = (k>>2)&1 (0=hi,1=lo), pair = k&3.
    #pragma unroll
    for (int d = 16, m = 8; d >= 2; d >>= 1, m >>= 1) {
        const bool up = (l & d) != 0;
        #pragma unroll
        for (int k = 0; k < m; ++k) {
            ull send = up ? acc[k] : acc[k + m];
            ull got  = __shfl_xor_sync(0xffffffffu, send, d);
            ull keep = up ? acc[k + m] : acc[k];
            acc[k] = add2(keep, got);
        }
    }
    acc[0] = add2(acc[0], __shfl_xor_sync(0xffffffffu, acc[0], 1));

    float fx, fy;
    asm("mov.b64 {%0, %1}, %2;" : "=f"(fx), "=f"(fy) : "l"(acc[0]));
    const int k    = l >> 1;
    const int rp   = k >> 3, half = (k >> 2) & 1, pair = k & 3;
    const int o    = (r0 + rp + half * 32) * CDIM + c;
    const int b    = 2 * pair + (l & 1);
    atomicAdd(out + b * OUTD + o, (l & 1) ? fy : fx);
}

// ---------------------------------------------------------------------------
extern "C" void kernel_launch(void* const* d_in, const int* in_sizes, int n_in,
                              void* d_out, int out_size) {
    const int*   Wq    = (const int*)  d_in[0];
    const float* scale = (const float*)d_in[1];
    const float* zero  = (const float*)d_in[2];
    const float* x     = (const float*)d_in[3];
    const float* bias  = (const float*)d_in[4];
    float* out = (float*)d_out;

    init_out_kernel<<<(NB * OUTD + 255) / 256, 256>>>(bias, out);
    hqq_gemv_kernel<<<CDIM * (IND / ICHUNK) * 2, 256>>>(Wq, scale, zero, x, out);
}